// round 6
// baseline (speedup 1.0000x reference)
#include <cuda_runtime.h>
#include <stdint.h>

// PluginEmbedding: sparse embedding lookup + per-row sum combine.
//   d_in[0] table         float32 [1000000, 128]
//   d_in[1] row_offsets   int32   [212993]
//   d_in[2] value_tensors int32   [212992]
// Output: float32 [212992, 128]
//
// R5 analysis: pipeline-bubble limited (DRAM 59%). This version: persistent
// warps, 8 rows in flight per warp, grid-stride over 8-row chunks with
// next-chunk offset/index prefetch so the meta chain is hidden one iteration
// ahead. Streaming stores preserve table L2 residency.

static constexpr int  kVec     = 128;           // floats per row
static constexpr int  kVocab   = 1000000;
static constexpr long long kNumRows = 8192LL * 26LL;  // 212992
static constexpr int  kChunk   = 8;             // rows per warp-iteration
static constexpr long long kNumChunks = kNumRows / kChunk; // 26624 (exact)

__global__ __launch_bounds__(256) void pe_gather_kernel(
    const float* __restrict__ table,
    const int*   __restrict__ row_offsets,
    const int*   __restrict__ vals,
    float*       __restrict__ out)
{
    const int lane = threadIdx.x & 31;
    const long long warpId =
        ((long long)blockIdx.x * blockDim.x + threadIdx.x) >> 5;
    const long long nWarps = ((long long)gridDim.x * blockDim.x) >> 5;

    long long c = warpId;
    if (c >= kNumChunks) return;

    // Prologue: metadata for first chunk.
    int offs[kChunk + 1], idx[kChunk];
#pragma unroll
    for (int u = 0; u <= kChunk; ++u)
        offs[u] = __ldg(&row_offsets[c * kChunk + u]);
#pragma unroll
    for (int u = 0; u < kChunk; ++u)
        idx[u] = (offs[u] < offs[u + 1]) ? __ldg(&vals[offs[u]]) : -1;

    for (;;) {
        const long long cn = c + nWarps;
        const bool has_next = (cn < kNumChunks);

        // 1) Issue the 8 independent table gathers (the MLP that matters).
        float4 v[kChunk];
#pragma unroll
        for (int u = 0; u < kChunk; ++u) {
            const int i = (idx[u] >= 0) ? min(idx[u], kVocab - 1) : 0;
            v[u] = __ldg(reinterpret_cast<const float4*>(
                       table + (long long)i * kVec) + lane);
        }

        // 2) Prefetch next chunk's metadata while table loads are in flight.
        int offsN[kChunk + 1], idxN[kChunk];
        if (has_next) {
#pragma unroll
            for (int u = 0; u <= kChunk; ++u)
                offsN[u] = __ldg(&row_offsets[cn * kChunk + u]);
#pragma unroll
            for (int u = 0; u < kChunk; ++u)
                idxN[u] = (offsN[u] < offsN[u + 1]) ? __ldg(&vals[offsN[u]]) : -1;
        }

        // 3) Finish rows: zero empty, accumulate generic nnz>1 tail (rare),
        //    streaming store.
#pragma unroll
        for (int u = 0; u < kChunk; ++u) {
            float4 acc = (idx[u] >= 0) ? v[u] : make_float4(0.f, 0.f, 0.f, 0.f);
            for (int j = offs[u] + 1; j < offs[u + 1]; ++j) {
                int i = __ldg(&vals[j]);
                i = min(max(i, 0), kVocab - 1);
                const float4 t = __ldg(reinterpret_cast<const float4*>(
                                     table + (long long)i * kVec) + lane);
                acc.x += t.x; acc.y += t.y; acc.z += t.z; acc.w += t.w;
            }
            __stcs(reinterpret_cast<float4*>(
                       out + (c * kChunk + u) * (long long)kVec) + lane, acc);
        }

        if (!has_next) break;
        c = cn;
#pragma unroll
        for (int u = 0; u <= kChunk; ++u) offs[u] = offsN[u];
#pragma unroll
        for (int u = 0; u < kChunk; ++u) idx[u] = idxN[u];
    }
}

extern "C" void kernel_launch(void* const* d_in, const int* in_sizes, int n_in,
                              void* d_out, int out_size)
{
    const float* table = (const float*)d_in[0];
    const int*   offs  = (const int*)d_in[1];
    const int*   vals  = (const int*)d_in[2];
    float*       out   = (float*)d_out;

    (void)in_sizes; (void)n_in; (void)out_size;

    // Persistent-ish: ~4 blocks per SM target; grid-stride absorbs any
    // occupancy shortfall. Each warp loops over ~7 chunks.
    const int block = 256;
    const int grid  = 592;   // 148 SMs * 4

    pe_gather_kernel<<<grid, block>>>(table, offs, vals, out);
}

// round 7
// speedup vs baseline: 1.1660x; 1.1660x over previous
#include <cuda_runtime.h>
#include <stdint.h>

// PluginEmbedding: sparse embedding lookup + per-row sum combine.
//   d_in[0] table         float32 [1000000, 128]
//   d_in[1] row_offsets   int32   [212993]
//   d_in[2] value_tensors int32   [212992]
// Output: float32 [212992, 128]
//
// R6 failed on register spills (regs=64, chunk=8 needs ~76). This version:
// identical software pipeline (persistent warps, next-chunk metadata prefetch
// hidden under the table-load window) but chunk=4 so everything fits in ~46
// regs. launch_bounds(256,5) pins the ceiling at 51 regs (spill canary: 64).

static constexpr int  kVec     = 128;                  // floats per row
static constexpr int  kVocab   = 1000000;
static constexpr long long kNumRows   = 8192LL * 26LL; // 212992
static constexpr int  kChunk   = 4;                    // rows per warp-iteration
static constexpr long long kNumChunks = kNumRows / kChunk; // 53248 (exact)

__global__ __launch_bounds__(256, 5) void pe_gather_kernel(
    const float* __restrict__ table,
    const int*   __restrict__ row_offsets,
    const int*   __restrict__ vals,
    float*       __restrict__ out)
{
    const int lane = threadIdx.x & 31;
    const long long warpId =
        ((long long)blockIdx.x * blockDim.x + threadIdx.x) >> 5;
    const long long nWarps = ((long long)gridDim.x * blockDim.x) >> 5;

    long long c = warpId;
    if (c >= kNumChunks) return;

    // Metadata for first chunk. row_offsets[c*4] is 16B-aligned -> int4 load.
    int offs[kChunk + 1], idx[kChunk];
    {
        const int4 o4 = __ldg(reinterpret_cast<const int4*>(row_offsets + c * kChunk));
        offs[0] = o4.x; offs[1] = o4.y; offs[2] = o4.z; offs[3] = o4.w;
        offs[4] = __ldg(row_offsets + c * kChunk + 4);
#pragma unroll
        for (int u = 0; u < kChunk; ++u)
            idx[u] = (offs[u] < offs[u + 1]) ? __ldg(&vals[offs[u]]) : -1;
    }

    for (;;) {
        const long long cn = c + nWarps;
        const bool has_next = (cn < kNumChunks);

        // 1) Issue the 4 independent 512B table gathers (front-batched MLP).
        float4 v[kChunk];
#pragma unroll
        for (int u = 0; u < kChunk; ++u) {
            const int i = (idx[u] >= 0) ? min(idx[u], kVocab - 1) : 0;
            v[u] = __ldg(reinterpret_cast<const float4*>(
                       table + (long long)i * kVec) + lane);
        }

        // 2) Prefetch next chunk's metadata under the table-load window.
        int offsN[kChunk + 1], idxN[kChunk];
        if (has_next) {
            const int4 o4 = __ldg(reinterpret_cast<const int4*>(row_offsets + cn * kChunk));
            offsN[0] = o4.x; offsN[1] = o4.y; offsN[2] = o4.z; offsN[3] = o4.w;
            offsN[4] = __ldg(row_offsets + cn * kChunk + 4);
#pragma unroll
            for (int u = 0; u < kChunk; ++u)
                idxN[u] = (offsN[u] < offsN[u + 1]) ? __ldg(&vals[offsN[u]]) : -1;
        }

        // 3) Finish rows: zero empty, generic nnz>1 tail (rare), streaming store.
#pragma unroll
        for (int u = 0; u < kChunk; ++u) {
            float4 acc = (idx[u] >= 0) ? v[u] : make_float4(0.f, 0.f, 0.f, 0.f);
            for (int j = offs[u] + 1; j < offs[u + 1]; ++j) {
                int i = __ldg(&vals[j]);
                i = min(max(i, 0), kVocab - 1);
                const float4 t = __ldg(reinterpret_cast<const float4*>(
                                     table + (long long)i * kVec) + lane);
                acc.x += t.x; acc.y += t.y; acc.z += t.z; acc.w += t.w;
            }
            __stcs(reinterpret_cast<float4*>(
                       out + (c * kChunk + u) * (long long)kVec) + lane, acc);
        }

        if (!has_next) break;
        c = cn;
#pragma unroll
        for (int u = 0; u <= kChunk; ++u) offs[u] = offsN[u];
#pragma unroll
        for (int u = 0; u < kChunk; ++u) idx[u] = idxN[u];
    }
}

extern "C" void kernel_launch(void* const* d_in, const int* in_sizes, int n_in,
                              void* d_out, int out_size)
{
    const float* table = (const float*)d_in[0];
    const int*   offs  = (const int*)d_in[1];
    const int*   vals  = (const int*)d_in[2];
    float*       out   = (float*)d_out;

    (void)in_sizes; (void)n_in; (void)out_size;

    // Persistent: 5 blocks/SM (reg-capped by launch_bounds), ~9 chunks/warp.
    const int block = 256;
    const int grid  = 148 * 5;   // 740

    pe_gather_kernel<<<grid, block>>>(table, offs, vals, out);
}

// round 9
// speedup vs baseline: 1.2110x; 1.0386x over previous
#include <cuda_runtime.h>
#include <stdint.h>

// PluginEmbedding: sparse embedding lookup + per-row sum combine.
//   d_in[0] table         float32 [1000000, 128]
//   d_in[1] row_offsets   int32   [212993]
//   d_in[2] value_tensors int32   [212992]
// Output: float32 [212992, 128]
//
// R7 analysis: per-iteration offs->idx->table chain was never broken (DRAM
// stuck ~58%). This version decouples metadata entirely: Phase A loads each
// block's 128 row metas (offsets + first index) into SMEM coalesced; Phase B
// reads indices from SMEM (29cyc) and issues 8 independent 512B table gathers
// per warp-batch. The only long-latency op in the hot loop is the gather.
// (Resubmission: R8 run hit an infra failure, design untested.)

static constexpr int  kVec          = 128;           // floats per row
static constexpr int  kVocab        = 1000000;
static constexpr long long kNumRows = 8192LL * 26LL; // 212992
static constexpr int  kRowsPerBlock = 128;           // 212992/128 = 1664 blocks
static constexpr int  kBatch        = 8;             // independent gathers in flight

__global__ __launch_bounds__(256, 4) void pe_gather_kernel(
    const float* __restrict__ table,
    const int*   __restrict__ row_offsets,
    const int*   __restrict__ vals,
    float*       __restrict__ out)
{
    __shared__ int s_idx[kRowsPerBlock];
    __shared__ int s_beg[kRowsPerBlock];
    __shared__ int s_end[kRowsPerBlock];

    const long long r0 = (long long)blockIdx.x * kRowsPerBlock;
    const int t = threadIdx.x;

    // Phase A: coalesced metadata stage (one dependent hop, paid once/block).
    if (t < kRowsPerBlock) {
        const int b = __ldg(&row_offsets[r0 + t]);
        const int e = __ldg(&row_offsets[r0 + t + 1]);
        s_beg[t] = b;
        s_end[t] = e;
        s_idx[t] = (b < e) ? __ldg(&vals[b]) : -1;
    }
    __syncthreads();

    // Phase B: each warp owns 16 rows -> 2 batches of 8 independent gathers.
    const int warp = t >> 5;
    const int lane = t & 31;

#pragma unroll
    for (int batch = 0; batch < 2; ++batch) {
        const int base = warp * 16 + batch * kBatch;

        int idx[kBatch];
#pragma unroll
        for (int u = 0; u < kBatch; ++u) idx[u] = s_idx[base + u];  // LDS bcast

        // 8 independent 512B gathers — the only DRAM-latency ops in the loop.
        float4 v[kBatch];
#pragma unroll
        for (int u = 0; u < kBatch; ++u) {
            const int i = (idx[u] >= 0) ? min(idx[u], kVocab - 1) : 0;
            v[u] = __ldg(reinterpret_cast<const float4*>(
                       table + (long long)i * kVec) + lane);
        }

#pragma unroll
        for (int u = 0; u < kBatch; ++u) {
            float4 acc = (idx[u] >= 0) ? v[u] : make_float4(0.f, 0.f, 0.f, 0.f);
            // Generic nnz>1 tail (absent in this dataset, kept for correctness).
            const int e = s_end[base + u];
            for (int j = s_beg[base + u] + 1; j < e; ++j) {
                int i = __ldg(&vals[j]);
                i = min(max(i, 0), kVocab - 1);
                const float4 tt = __ldg(reinterpret_cast<const float4*>(
                                      table + (long long)i * kVec) + lane);
                acc.x += tt.x; acc.y += tt.y; acc.z += tt.z; acc.w += tt.w;
            }
            __stcs(reinterpret_cast<float4*>(
                       out + (r0 + base + u) * (long long)kVec) + lane, acc);
        }
    }
}

extern "C" void kernel_launch(void* const* d_in, const int* in_sizes, int n_in,
                              void* d_out, int out_size)
{
    const float* table = (const float*)d_in[0];
    const int*   offs  = (const int*)d_in[1];
    const int*   vals  = (const int*)d_in[2];
    float*       out   = (float*)d_out;

    (void)in_sizes; (void)n_in; (void)out_size;

    const int block = 256;
    const long long grid = kNumRows / kRowsPerBlock;   // 1664 (exact)

    pe_gather_kernel<<<(unsigned)grid, block>>>(table, offs, vals, out);
}

// round 10
// speedup vs baseline: 1.2241x; 1.0108x over previous
#include <cuda_runtime.h>
#include <stdint.h>

// PluginEmbedding: sparse embedding lookup + per-row sum combine.
//   d_in[0] table         float32 [1000000, 128]
//   d_in[1] row_offsets   int32   [212993]
//   d_in[2] value_tensors int32   [212992]
// Output: float32 [212992, 128]
//
// Series analysis: DRAM% saturates ~60% for in-flight >= ~2.4 rows/warp-slot;
// app-level throughput is ~82% of HBM spec -> near the random-512B-gather
// roofline. This round: same SMEM-metadata design as R9 but batch=4 (no
// register spill; R9 hit the 64-reg cap), higher occupancy ceiling, and
// 32-bit byte addressing to trim IMAD.WIDE chains.

static constexpr int  kVocab        = 1000000;
static constexpr long long kNumRows = 8192LL * 26LL; // 212992
static constexpr int  kRowsPerBlock = 128;           // 1664 blocks (exact)
static constexpr int  kBatch        = 4;             // gathers in flight / warp
static constexpr int  kRowBytes     = 512;           // 128 floats

__global__ __launch_bounds__(256, 6) void pe_gather_kernel(
    const float* __restrict__ table,
    const int*   __restrict__ row_offsets,
    const int*   __restrict__ vals,
    float*       __restrict__ out)
{
    __shared__ int s_idx[kRowsPerBlock];
    __shared__ int s_beg[kRowsPerBlock];
    __shared__ int s_end[kRowsPerBlock];

    const int t = threadIdx.x;
    const unsigned blockRow0 = blockIdx.x * kRowsPerBlock;

    // Phase A: coalesced metadata stage (one dependent hop, once per block,
    // overlapped across the ~6 resident blocks per SM).
    if (t < kRowsPerBlock) {
        const int b = __ldg(&row_offsets[blockRow0 + t]);
        const int e = __ldg(&row_offsets[blockRow0 + t + 1]);
        s_beg[t] = b;
        s_end[t] = e;
        s_idx[t] = (b < e) ? __ldg(&vals[b]) : -1;
    }
    __syncthreads();

    const int warp = t >> 5;
    const int lane = t & 31;
    const char* tbl = reinterpret_cast<const char*>(table);
    char*       o   = reinterpret_cast<char*>(out);
    const unsigned laneOff = (unsigned)lane * 16u;

    // Phase B: warp owns 16 rows -> 4 batches of 4 independent 512B gathers.
#pragma unroll
    for (int batch = 0; batch < 4; ++batch) {
        const int base = warp * 16 + batch * kBatch;

        int idx[kBatch];
#pragma unroll
        for (int u = 0; u < kBatch; ++u) idx[u] = s_idx[base + u];  // LDS bcast

        // 4 independent 512B gathers — only DRAM-latency ops in the loop.
        // All byte offsets fit in 32 bits (table 512MB, out 109MB).
        float4 v[kBatch];
#pragma unroll
        for (int u = 0; u < kBatch; ++u) {
            const unsigned i = (unsigned)((idx[u] >= 0) ? min(idx[u], kVocab - 1) : 0);
            v[u] = __ldg(reinterpret_cast<const float4*>(
                       tbl + i * (unsigned)kRowBytes + laneOff));
        }

#pragma unroll
        for (int u = 0; u < kBatch; ++u) {
            float4 acc = (idx[u] >= 0) ? v[u] : make_float4(0.f, 0.f, 0.f, 0.f);
            // Generic nnz>1 tail (absent in this dataset, kept for correctness).
            const int e = s_end[base + u];
            for (int j = s_beg[base + u] + 1; j < e; ++j) {
                int i = __ldg(&vals[j]);
                i = min(max(i, 0), kVocab - 1);
                const float4 tt = __ldg(reinterpret_cast<const float4*>(
                                      tbl + (unsigned)i * (unsigned)kRowBytes + laneOff));
                acc.x += tt.x; acc.y += tt.y; acc.z += tt.z; acc.w += tt.w;
            }
            const unsigned row = blockRow0 + (unsigned)(base + u);
            __stcs(reinterpret_cast<float4*>(
                       o + row * (unsigned)kRowBytes + laneOff), acc);
        }
    }
}

extern "C" void kernel_launch(void* const* d_in, const int* in_sizes, int n_in,
                              void* d_out, int out_size)
{
    const float* table = (const float*)d_in[0];
    const int*   offs  = (const int*)d_in[1];
    const int*   vals  = (const int*)d_in[2];
    float*       out   = (float*)d_out;

    (void)in_sizes; (void)n_in; (void)out_size;

    const int block = 256;
    const unsigned grid = (unsigned)(kNumRows / kRowsPerBlock);   // 1664

    pe_gather_kernel<<<grid, block>>>(table, offs, vals, out);
}